// round 5
// baseline (speedup 1.0000x reference)
#include <cuda_runtime.h>
#include <math.h>

#define Bb 256
#define Tt 128
#define Vv 512
#define Ee 64
#define Hh 256
#define G4 1024
#define KD 320
#define NB 128
#define NT 256

#define KT 32
#define NKT_E 8
#define NKT_D 10

// dynamic shared layout (floats)
#define WSR_FLOATS (KD * 32 * 2)            // 20480 floats: [320][32] float2 pairs
#define AST 68
#define AS_BUF (KT * AST)                   // 2176 floats per buffer
#define AS_REGION 16512                     // max(2*AS_BUF, phase2 hs2 = 32*258*2)
#define SIDX_OFF (WSR_FLOATS + AS_REGION)   // 36992
#define DSM_FLOATS (SIDX_OFF + 64)          // 37056
#define DSM_BYTES (DSM_FLOATS * 4)          // 148224

// ---------------- device scratch ----------------
__device__ float g_Gx[(size_t)Bb * Tt * G4];
__device__ float g_Xe[(size_t)Bb * Tt * Ee];
__device__ float g_WeT[Vv * Ee];
__device__ float g_WihTpE[Ee * G4];
__device__ float2 g_WhhR[(size_t)Hh * G4];   // replicated pairs {w,w}
__device__ float2 g_WsDR[(size_t)KD * G4];   // replicated pairs {w,w}
__device__ float g_biasE[G4];
__device__ float g_biasD[G4];
__device__ float g_WoT[Hh * Vv];
__device__ float g_WdT[Vv * Ee];
__device__ float g_WdTb[Vv * Ee];
__device__ float g_h[2][Bb * Hh];
__device__ float g_emb[Bb * Ee];
__device__ float g_av16[16 * Bb];
__device__ int   g_ai16[16 * Bb];
__device__ unsigned g_cnt = 0;
__device__ unsigned g_gen = 0;

// ---------------- helpers ----------------
__device__ __forceinline__ float ldcg(const float* p) {
    float v; asm volatile("ld.global.cg.f32 %0, [%1];" : "=f"(v) : "l"(p)); return v;
}
__device__ __forceinline__ int ldcg_i(const int* p) {
    int v; asm volatile("ld.global.cg.s32 %0, [%1];" : "=r"(v) : "l"(p)); return v;
}
__device__ __forceinline__ void stcg(float* p, float v) {
    asm volatile("st.global.cg.f32 [%0], %1;" :: "l"(p), "f"(v));
}
__device__ __forceinline__ void stcg_i(int* p, int v) {
    asm volatile("st.global.cg.s32 [%0], %1;" :: "l"(p), "r"(v));
}
__device__ __forceinline__ float sigm(float x) { return 1.0f / (1.0f + expf(-x)); }

__device__ __forceinline__ void ffma2(unsigned long long& d, unsigned long long a,
                                      unsigned long long b) {
    asm("fma.rn.f32x2 %0, %1, %2, %0;" : "+l"(d) : "l"(a), "l"(b));
}
__device__ __forceinline__ unsigned long long pk(float lo, float hi) {
    unsigned long long r; asm("mov.b64 %0, {%1,%2};" : "=l"(r) : "f"(lo), "f"(hi)); return r;
}
__device__ __forceinline__ void upk(unsigned long long v, float& lo, float& hi) {
    asm("mov.b64 {%0,%1}, %2;" : "=f"(lo), "=f"(hi) : "l"(v));
}

__device__ __forceinline__ void grid_bar() {
    __threadfence();
    __syncthreads();
    if (threadIdx.x == 0) {
        unsigned gen = *((volatile unsigned*)&g_gen);
        __threadfence();
        if (atomicAdd(&g_cnt, 1u) == (unsigned)(NB - 1)) {
            g_cnt = 0;
            __threadfence();
            atomicExch(&g_gen, gen + 1u);
        } else {
            int spins = 0;
            while (*((volatile unsigned*)&g_gen) == gen) {
                if (++spins > 8192) { __nanosleep(64); spins = 0; }
            }
        }
    }
    __syncthreads();
}

// ---------------- pack weights ----------------
// packed col p: q = p&3 (i,f,g,o), j = p>>2 ; orig gate row = q*H + j
__global__ void pack_kernel(const float* __restrict__ We,
                            const float* __restrict__ Wih_e, const float* __restrict__ Whh_e,
                            const float* __restrict__ bih_e, const float* __restrict__ bhh_e,
                            const float* __restrict__ Wd, const float* __restrict__ bd,
                            const float* __restrict__ Wih_d, const float* __restrict__ Whh_d,
                            const float* __restrict__ bih_d, const float* __restrict__ bhh_d,
                            const float* __restrict__ Wo) {
    const int R0 = Hh * G4;          // WhhR
    const int R1 = R0 + KD * G4;     // WsDR
    const int R2 = R1 + Ee * G4;     // WihTpE
    const int R3 = R2 + Hh * Vv;     // WoT
    const int R4 = R3 + Vv * Ee;     // WdT
    const int R5 = R4 + Vv * Ee;     // WdTb
    const int R6 = R5 + Vv * Ee;     // WeT
    const int R7 = R6 + G4;          // biasE
    const int R8 = R7 + G4;          // biasD
    for (int id = blockIdx.x * blockDim.x + threadIdx.x; id < R8; id += gridDim.x * blockDim.x) {
        if (id < R0) {
            int k = id / G4, p = id % G4, q = p & 3, j = p >> 2;
            float w = Whh_e[(q * Hh + j) * Hh + k];
            g_WhhR[id] = make_float2(w, w);
        } else if (id < R1) {
            int t = id - R0; int k = t / G4, p = t % G4, q = p & 3, j = p >> 2;
            float w = (k < Ee) ? Wih_d[(q * Hh + j) * Ee + k]
                               : Whh_d[(q * Hh + j) * Hh + (k - Ee)];
            g_WsDR[t] = make_float2(w, w);
        } else if (id < R2) {
            int t = id - R1; int e = t / G4, p = t % G4, q = p & 3, j = p >> 2;
            g_WihTpE[t] = Wih_e[(q * Hh + j) * Ee + e];
        } else if (id < R3) {
            int t = id - R2; int k = t / Vv, v = t % Vv;
            g_WoT[t] = Wo[v * Hh + k];
        } else if (id < R4) {
            int t = id - R3; int v = t / Ee, e = t % Ee;
            g_WdT[t] = Wd[e * Vv + v];
        } else if (id < R5) {
            int t = id - R4; int v = t / Ee, e = t % Ee;
            g_WdTb[t] = Wd[e * Vv + v] + bd[e];
        } else if (id < R6) {
            int t = id - R5; int v = t / Ee, e = t % Ee;
            g_WeT[t] = We[e * Vv + v];
        } else if (id < R7) {
            int p = id - R6, q = p & 3, j = p >> 2;
            g_biasE[p] = bih_e[q * Hh + j] + bhh_e[q * Hh + j];
        } else {
            int p = id - R7, q = p & 3, j = p >> 2;
            g_biasD[p] = bih_d[q * Hh + j] + bhh_d[q * Hh + j];
        }
    }
}

// ---------------- Xe = x @ We^T + be ----------------
__global__ void __launch_bounds__(256) xe_kernel(const float* __restrict__ x,
                                                 const float* __restrict__ be) {
    __shared__ float As[32][65];
    __shared__ float Bs[32][64];
    int tid = threadIdx.x;
    int tx = tid & 15, ty = tid >> 4;
    int m0 = blockIdx.x * 64;
    float acc[4][4];
#pragma unroll
    for (int c = 0; c < 4; c++) {
        float b = be[tx * 4 + c];
#pragma unroll
        for (int r = 0; r < 4; r++) acc[r][c] = b;
    }
    for (int kt = 0; kt < 16; ++kt) {
        int k0 = kt * 32;
        {
            int kk = tid & 31, mm = tid >> 5;
#pragma unroll
            for (int p = 0; p < 8; p++) {
                int m = mm + p * 8;
                As[kk][m] = x[(size_t)(m0 + m) * Vv + k0 + kk];
            }
        }
        {
            int ee = tid & 63, kk = tid >> 6;
#pragma unroll
            for (int p = 0; p < 8; p++) {
                int k = kk + p * 4;
                Bs[k][ee] = g_WeT[(size_t)(k0 + k) * Ee + ee];
            }
        }
        __syncthreads();
#pragma unroll
        for (int kk = 0; kk < 32; kk++) {
            float a[4], b[4];
#pragma unroll
            for (int r = 0; r < 4; r++) a[r] = As[kk][ty * 4 + r];
#pragma unroll
            for (int c = 0; c < 4; c++) b[c] = Bs[kk][tx * 4 + c];
#pragma unroll
            for (int r = 0; r < 4; r++)
#pragma unroll
                for (int c = 0; c < 4; c++) acc[r][c] += a[r] * b[c];
        }
        __syncthreads();
    }
#pragma unroll
    for (int r = 0; r < 4; r++) {
        int m = m0 + ty * 4 + r;
#pragma unroll
        for (int c = 0; c < 4; c++) g_Xe[(size_t)m * Ee + tx * 4 + c] = acc[r][c];
    }
}

// ---------------- Gx = Xe @ WihTpE + biasE ----------------
__global__ void __launch_bounds__(256) gx_kernel() {
    __shared__ float As[64][65];
    __shared__ float Bs[64][64];
    int tid = threadIdx.x;
    int tx = tid & 15, ty = tid >> 4;
    int m0 = blockIdx.x * 64;
    int n0 = blockIdx.y * 64;
    {
        int kk = tid & 63, mm = tid >> 6;
#pragma unroll
        for (int p = 0; p < 16; p++) {
            int m = mm + p * 4;
            As[kk][m] = g_Xe[(size_t)(m0 + m) * Ee + kk];
        }
    }
    {
        int nn = tid & 63, kk = tid >> 6;
#pragma unroll
        for (int p = 0; p < 16; p++) {
            int k = kk + p * 4;
            Bs[k][nn] = g_WihTpE[(size_t)k * G4 + n0 + nn];
        }
    }
    __syncthreads();
    float acc[4][4];
#pragma unroll
    for (int c = 0; c < 4; c++) {
        float b = g_biasE[n0 + tx * 4 + c];
#pragma unroll
        for (int r = 0; r < 4; r++) acc[r][c] = b;
    }
#pragma unroll
    for (int kk = 0; kk < 64; kk++) {
        float a[4], b[4];
#pragma unroll
        for (int r = 0; r < 4; r++) a[r] = As[kk][ty * 4 + r];
#pragma unroll
        for (int c = 0; c < 4; c++) b[c] = Bs[kk][tx * 4 + c];
#pragma unroll
        for (int r = 0; r < 4; r++)
#pragma unroll
            for (int c = 0; c < 4; c++) acc[r][c] += a[r] * b[c];
    }
#pragma unroll
    for (int r = 0; r < 4; r++) {
        int bt = m0 + ty * 4 + r;
        int b = bt >> 7, t = bt & 127;
        size_t base = ((size_t)t * Bb + b) * G4 + n0 + tx * 4;
#pragma unroll
        for (int c = 0; c < 4; c++) g_Gx[base + c] = acc[r][c];
    }
}

// ---------------- emb0 ----------------
__global__ void emb0_kernel(const float* __restrict__ x, const float* __restrict__ bd) {
    __shared__ float x0[Vv];
    int b = blockIdx.x, tid = threadIdx.x; // 64 threads
    for (int i = tid; i < Vv; i += 64) x0[i] = x[(size_t)b * Tt * Vv + i];
    __syncthreads();
    float acc = bd[tid];
    for (int v = 0; v < Vv; v++) acc += x0[v] * g_WdT[(size_t)v * Ee + tid];
    g_emb[b * Ee + tid] = acc;
}

// ---------------- init ----------------
__global__ void init_kernel(const int* __restrict__ xlens, float* __restrict__ out,
                            int write_extra) {
    int id = blockIdx.x * blockDim.x + threadIdx.x;
    if (id < Bb * Vv) {
        int b = id / Vv, v = id % Vv;
        out[(size_t)b * Tt * Vv + v] = 0.f;
    }
    if (write_extra && id < Bb) out[(size_t)Bb * Tt * Vv + id] = (float)xlens[id];
    if (id < Bb * Hh) { g_h[0][id] = 0.f; g_h[1][id] = 0.f; }
}

// ---------------- persistent recurrent kernel ----------------
__global__ void __launch_bounds__(NT, 1) rec_kernel(const int* __restrict__ xlens,
                                                    const float* __restrict__ bo,
                                                    float* __restrict__ out,
                                                    int write_extra) {
    extern __shared__ float dsm[];
    unsigned long long* Wsr = (unsigned long long*)dsm;       // [K][32] pairs
    float* As = dsm + WSR_FLOATS;                             // 2 x [32][68] double buffer
    int* sIdx = (int*)(dsm + SIDX_OFF);                       // [64]
    unsigned long long* hs2 = (unsigned long long*)As;        // [32][258] pairs (phase2 overlay)

    const int tid = threadIdx.x, bx = blockIdx.x;
    const int tx = tid & 15, ty = tid >> 4;
    const int m0 = (bx >> 5) * 64;
    const int n0 = (bx & 31) * 32;
    const int row0 = m0 + ty * 4;
    const int col0 = n0 + tx * 2;
    const bool evenT = ((tx & 1) == 0);
    const int junit = col0 >> 2;
    const int skk = tid & 31, smm = tid >> 5;

    float c_reg[4] = {0.f, 0.f, 0.f, 0.f};
    float h_reg[4] = {0.f, 0.f, 0.f, 0.f};
    int lens[4];
#pragma unroll
    for (int r = 0; r < 4; r++) lens[r] = xlens[row0 + r];

    const unsigned FULL = 0xffffffffu;
    int par = 0;

    // ---- stage encoder Whh pairs [256][32] into smem ----
    for (int i = tid; i < Hh * 32; i += NT) {
        int k = i >> 5, n = i & 31;
        float2 w = g_WhhR[(size_t)k * G4 + n0 + n];
        Wsr[k * 32 + n] = *(unsigned long long*)&w;
    }
    __syncthreads();

    // ======================= encoder =======================
    for (int t = 0; t < Tt; ++t) {
        const float* gx = g_Gx + ((size_t)t * Bb) * G4;
        unsigned long long acc00, acc01, acc10, acc11;
        {
            float a0 = __ldg(&gx[(size_t)(row0 + 0) * G4 + col0]);
            float a1 = __ldg(&gx[(size_t)(row0 + 1) * G4 + col0]);
            float a2 = __ldg(&gx[(size_t)(row0 + 2) * G4 + col0]);
            float a3 = __ldg(&gx[(size_t)(row0 + 3) * G4 + col0]);
            float b0 = __ldg(&gx[(size_t)(row0 + 0) * G4 + col0 + 1]);
            float b1 = __ldg(&gx[(size_t)(row0 + 1) * G4 + col0 + 1]);
            float b2 = __ldg(&gx[(size_t)(row0 + 2) * G4 + col0 + 1]);
            float b3 = __ldg(&gx[(size_t)(row0 + 3) * G4 + col0 + 1]);
            acc00 = pk(a0, a1); acc10 = pk(a2, a3);
            acc01 = pk(b0, b1); acc11 = pk(b2, b3);
        }
        const float* hbuf = g_h[par];
        // stage ktile 0 (double-buffered pipeline)
        {
            const float* src = hbuf + (size_t)(m0 + smm) * Hh + skk;
            float* dst = As + skk * AST + smm;
#pragma unroll
            for (int p = 0; p < 8; p++) dst[p * 8] = ldcg(src + (size_t)(p * 8) * Hh);
        }
        __syncthreads();
        int buf = 0;
        for (int kt = 0; kt < NKT_E; ++kt) {
            if (kt + 1 < NKT_E) {
                int k0n = (kt + 1) * KT;
                const float* src = hbuf + (size_t)(m0 + smm) * Hh + k0n + skk;
                float* dst = As + (buf ^ 1) * AS_BUF + skk * AST + smm;
#pragma unroll
                for (int p = 0; p < 8; p++) dst[p * 8] = ldcg(src + (size_t)(p * 8) * Hh);
            }
            const float* Ab = As + buf * AS_BUF;
            const unsigned long long* Wk = Wsr + (kt * KT) * 32;
#pragma unroll
            for (int kk = 0; kk < KT; kk++) {
                ulonglong2 av = *(const ulonglong2*)(Ab + kk * AST + ty * 4);
                ulonglong2 bv = *(const ulonglong2*)(Wk + kk * 32 + tx * 2);
                ffma2(acc00, av.x, bv.x); ffma2(acc01, av.x, bv.y);
                ffma2(acc10, av.y, bv.x); ffma2(acc11, av.y, bv.y);
            }
            __syncthreads();
            buf ^= 1;
        }
        float acc[4][2];
        upk(acc00, acc[0][0], acc[1][0]); upk(acc01, acc[0][1], acc[1][1]);
        upk(acc10, acc[2][0], acc[3][0]); upk(acc11, acc[2][1], acc[3][1]);
#pragma unroll
        for (int r = 0; r < 4; r++) {
            float gg = __shfl_down_sync(FULL, acc[r][0], 1);
            float go = __shfl_down_sync(FULL, acc[r][1], 1);
            if (evenT) {
                float i_ = sigm(acc[r][0]), f_ = sigm(acc[r][1]);
                float gv = tanhf(gg), o_ = sigm(go);
                float cn = f_ * c_reg[r] + i_ * gv;
                float hn = o_ * tanhf(cn);
                bool msk = (t < lens[r]);
                c_reg[r] = msk ? cn : c_reg[r];
                float hv = msk ? hn : h_reg[r];
                h_reg[r] = hv;
                stcg(&g_h[par ^ 1][(size_t)(row0 + r) * Hh + junit], hv);
            }
        }
        grid_bar();
        par ^= 1;
    }

    if (write_extra && evenT) {
#pragma unroll
        for (int r = 0; r < 4; r++)
            out[(size_t)Bb * Tt * Vv + Bb + (size_t)(row0 + r) * Hh + junit] = h_reg[r];
    }

    // ---- stage decoder stacked weight pairs [320][32] ----
    __syncthreads();
    for (int i = tid; i < KD * 32; i += NT) {
        int k = i >> 5, n = i & 31;
        float2 w = g_WsDR[(size_t)k * G4 + n0 + n];
        Wsr[k * 32 + n] = *(unsigned long long*)&w;
    }
    const unsigned long long bD0rep = pk(g_biasD[col0], g_biasD[col0]);
    const unsigned long long bD1rep = pk(g_biasD[col0 + 1], g_biasD[col0 + 1]);
    // phase2 constants: 16 col groups x 8 row groups
    const int colg = bx & 15, rowg = bx >> 4;
    const int r0p2 = rowg * 32;
    const int t16 = tid & 15, rq = tid >> 4;
    const int rA = r0p2 + rq * 2, rB = rA + 1;
    const int cpair = colg * 32 + t16 * 2;
    const unsigned long long boP = *(const unsigned long long*)&bo[cpair];
    __syncthreads();

    // ======================= decoder =======================
    for (int s = 0; s < Tt - 1; ++s) {
        // combine group argmaxes from previous step
        if (s > 0) {
            if (tid < 64) {
                int row = m0 + tid;
                float best = ldcg(&g_av16[row]); int bi = ldcg_i(&g_ai16[row]);
#pragma unroll
                for (int g = 1; g < 16; g++) {
                    float v = ldcg(&g_av16[g * Bb + row]);
                    int ix = ldcg_i(&g_ai16[g * Bb + row]);
                    if (v > best) { best = v; bi = ix; }
                }
                sIdx[tid] = bi;
            }
            __syncthreads();
        }

        unsigned long long acc00 = bD0rep, acc01 = bD1rep, acc10 = bD0rep, acc11 = bD1rep;
        const float* hbuf = g_h[par];

        // stage ktile 0 (emb region)
        {
            float* dst = As + skk * AST + smm;
            if (s == 0) {
                const float* src = g_emb + (size_t)(m0 + smm) * Ee + skk;
#pragma unroll
                for (int p = 0; p < 8; p++) dst[p * 8] = ldcg(src + (size_t)(p * 8) * Ee);
            } else {
#pragma unroll
                for (int p = 0; p < 8; p++) {
                    int idx = sIdx[smm + p * 8];
                    dst[p * 8] = __ldg(&g_WdTb[(size_t)idx * Ee + skk]);
                }
            }
        }
        __syncthreads();
        int buf = 0;
        for (int kt = 0; kt < NKT_D; ++kt) {
            if (kt + 1 < NKT_D) {
                int k0n = (kt + 1) * KT;
                float* dst = As + (buf ^ 1) * AS_BUF + skk * AST + smm;
                if (k0n < Ee) {
                    if (s == 0) {
                        const float* src = g_emb + (size_t)(m0 + smm) * Ee + k0n + skk;
#pragma unroll
                        for (int p = 0; p < 8; p++) dst[p * 8] = ldcg(src + (size_t)(p * 8) * Ee);
                    } else {
#pragma unroll
                        for (int p = 0; p < 8; p++) {
                            int idx = sIdx[smm + p * 8];
                            dst[p * 8] = __ldg(&g_WdTb[(size_t)idx * Ee + k0n + skk]);
                        }
                    }
                } else {
                    const float* src = hbuf + (size_t)(m0 + smm) * Hh + (k0n - Ee) + skk;
#pragma unroll
                    for (int p = 0; p < 8; p++) dst[p * 8] = ldcg(src + (size_t)(p * 8) * Hh);
                }
            }
            const float* Ab = As + buf * AS_BUF;
            const unsigned long long* Wk = Wsr + (kt * KT) * 32;
#pragma unroll
            for (int kk = 0; kk < KT; kk++) {
                ulonglong2 av = *(const ulonglong2*)(Ab + kk * AST + ty * 4);
                ulonglong2 bv = *(const ulonglong2*)(Wk + kk * 32 + tx * 2);
                ffma2(acc00, av.x, bv.x); ffma2(acc01, av.x, bv.y);
                ffma2(acc10, av.y, bv.x); ffma2(acc11, av.y, bv.y);
            }
            __syncthreads();
            buf ^= 1;
        }
        float acc[4][2];
        upk(acc00, acc[0][0], acc[1][0]); upk(acc01, acc[0][1], acc[1][1]);
        upk(acc10, acc[2][0], acc[3][0]); upk(acc11, acc[2][1], acc[3][1]);
#pragma unroll
        for (int r = 0; r < 4; r++) {
            float gg = __shfl_down_sync(FULL, acc[r][0], 1);
            float go = __shfl_down_sync(FULL, acc[r][1], 1);
            if (evenT) {
                float i_ = sigm(acc[r][0]), f_ = sigm(acc[r][1]);
                float gv = tanhf(gg), o_ = sigm(go);
                float cn = f_ * c_reg[r] + i_ * gv;
                float hn = o_ * tanhf(cn);
                c_reg[r] = cn;
                h_reg[r] = hn;
                stcg(&g_h[par ^ 1][(size_t)(row0 + r) * Hh + junit], hn);
            }
        }
        grid_bar();
        par ^= 1;

        // ---- phase2: logits, 32 rows x 32 cols per block ----
        {
            const float* hb = g_h[par];
            {
                int row = tid >> 3, kb = tid & 7;
                const float* src = hb + (size_t)(r0p2 + row) * Hh + kb;
                unsigned long long* dst = hs2 + row * 258 + kb;
#pragma unroll
                for (int q = 0; q < 32; q++) {
                    float v = ldcg(src + q * 8);
                    dst[q * 8] = pk(v, v);
                }
            }
            __syncthreads();
            unsigned long long accA = boP, accB = boP;
            const unsigned long long* hA = hs2 + rq * 2 * 258;
            const unsigned long long* hB = hA + 258;
#pragma unroll 8
            for (int k = 0; k < Hh; k++) {
                unsigned long long wp =
                    *(const unsigned long long*)&g_WoT[(size_t)k * Vv + cpair];
                ffma2(accA, hA[k], wp);
                ffma2(accB, hB[k], wp);
            }
            float a0, a1, b0f, b1f;
            upk(accA, a0, a1); upk(accB, b0f, b1f);
            size_t ybA = (size_t)rA * Tt * Vv + (size_t)(s + 1) * Vv + cpair;
            size_t ybB = (size_t)rB * Tt * Vv + (size_t)(s + 1) * Vv + cpair;
            *(float2*)&out[ybA] = make_float2(a0, a1);
            *(float2*)&out[ybB] = make_float2(b0f, b1f);
            // local argmax over 2 cols, reduce over 16 lanes
            float vA = a0; int iA = cpair; if (a1 > vA) { vA = a1; iA = cpair + 1; }
            float vB = b0f; int iB = cpair; if (b1f > vB) { vB = b1f; iB = cpair + 1; }
#pragma unroll
            for (int off = 8; off > 0; off >>= 1) {
                float ov = __shfl_down_sync(FULL, vA, off, 16);
                int oi = __shfl_down_sync(FULL, iA, off, 16);
                if (ov > vA || (ov == vA && oi < iA)) { vA = ov; iA = oi; }
                ov = __shfl_down_sync(FULL, vB, off, 16);
                oi = __shfl_down_sync(FULL, iB, off, 16);
                if (ov > vB || (ov == vB && oi < iB)) { vB = ov; iB = oi; }
            }
            if (t16 == 0) {
                stcg(&g_av16[colg * Bb + rA], vA);
                stcg_i(&g_ai16[colg * Bb + rA], iA);
                stcg(&g_av16[colg * Bb + rB], vB);
                stcg_i(&g_ai16[colg * Bb + rB], iB);
            }
        }
        grid_bar();
    }
}

// ---------------- launch ----------------
extern "C" void kernel_launch(void* const* d_in, const int* in_sizes, int n_in,
                              void* d_out, int out_size) {
    (void)in_sizes; (void)n_in;
    const float* x     = (const float*)d_in[0];
    const int*   xlens = (const int*)  d_in[1];
    const float* We    = (const float*)d_in[2];
    const float* be    = (const float*)d_in[3];
    const float* Wih_e = (const float*)d_in[4];
    const float* Whh_e = (const float*)d_in[5];
    const float* bih_e = (const float*)d_in[6];
    const float* bhh_e = (const float*)d_in[7];
    const float* Wd    = (const float*)d_in[8];
    const float* bd    = (const float*)d_in[9];
    const float* Wih_d = (const float*)d_in[10];
    const float* Whh_d = (const float*)d_in[11];
    const float* bih_d = (const float*)d_in[12];
    const float* bhh_d = (const float*)d_in[13];
    const float* Wo    = (const float*)d_in[14];
    const float* bo    = (const float*)d_in[15];
    float* out = (float*)d_out;

    int write_extra = (out_size >= Bb * Tt * Vv + Bb + Bb * Hh) ? 1 : 0;

    cudaFuncSetAttribute(rec_kernel, cudaFuncAttributeMaxDynamicSharedMemorySize, DSM_BYTES);

    pack_kernel<<<1024, 256>>>(We, Wih_e, Whh_e, bih_e, bhh_e,
                               Wd, bd, Wih_d, Whh_d, bih_d, bhh_d, Wo);
    xe_kernel<<<512, 256>>>(x, be);
    gx_kernel<<<dim3(512, 16), 256>>>();
    emb0_kernel<<<Bb, 64>>>(x, bd);
    init_kernel<<<512, 256>>>(xlens, out, write_extra);
    rec_kernel<<<NB, NT, DSM_BYTES>>>(xlens, bo, out, write_extra);
}

// round 11
// speedup vs baseline: 1.2589x; 1.2589x over previous
#include <cuda_runtime.h>
#include <math.h>

#define Bb 256
#define Tt 128
#define Vv 512
#define Ee 64
#define Hh 256
#define G4 1024
#define KD 320
#define NB 128
#define NT 256

#define KT 32
#define NKT_E 8
#define NKT_D 10

// dynamic shared layout (floats)
#define WS_STRIDE 34
#define WS_FLOATS (KD * WS_STRIDE)          // 10880
#define AST 66
#define AS_OFF WS_FLOATS
#define AS_BUF (KT * AST)                   // 2112
#define WOS_OFF (AS_OFF + 2 * AS_BUF)       // 15104
#define WOS_STRIDE 34
#define WOS_FLOATS (Hh * WOS_STRIDE)        // 8704
#define HS_OFF (WOS_OFF + WOS_FLOATS)       // 23808
#define HS_STRIDE 264
#define HS_FLOATS (32 * HS_STRIDE)          // 8448
#define SIDX_OFF (HS_OFF + HS_FLOATS)       // 32256
#define DSM_FLOATS (SIDX_OFF + 64)          // 32320
#define DSM_BYTES (DSM_FLOATS * 4)          // 129280

// ---------------- device scratch ----------------
__device__ __align__(16) float g_Gx[(size_t)Bb * Tt * G4];
__device__ __align__(16) float g_Xe[(size_t)Bb * Tt * Ee];
__device__ __align__(16) float g_WeT[Vv * Ee];
__device__ __align__(16) float g_WihTpE[Ee * G4];
__device__ __align__(16) float g_WhhTpE[Hh * G4];
__device__ __align__(16) float g_biasE[G4];
__device__ __align__(16) float g_WsTpD[KD * G4];
__device__ __align__(16) float g_biasD[G4];
__device__ __align__(16) float g_WoT[Hh * Vv];
__device__ __align__(16) float g_WdT[Vv * Ee];
__device__ __align__(16) float g_WdTb[Vv * Ee];
__device__ __align__(16) float g_h[2][Bb * Hh];
__device__ __align__(16) float g_emb[Bb * Ee];
__device__ __align__(16) float g_av16[16 * Bb];
__device__ __align__(16) int   g_ai16[16 * Bb];
__device__ unsigned g_cnt = 0;
__device__ unsigned g_gen = 0;

// ---------------- helpers ----------------
__device__ __forceinline__ float ldcg(const float* p) {
    float v; asm volatile("ld.global.cg.f32 %0, [%1];" : "=f"(v) : "l"(p)); return v;
}
__device__ __forceinline__ int ldcg_i(const int* p) {
    int v; asm volatile("ld.global.cg.s32 %0, [%1];" : "=r"(v) : "l"(p)); return v;
}
__device__ __forceinline__ void stcg(float* p, float v) {
    asm volatile("st.global.cg.f32 [%0], %1;" :: "l"(p), "f"(v));
}
__device__ __forceinline__ void stcg_i(int* p, int v) {
    asm volatile("st.global.cg.s32 [%0], %1;" :: "l"(p), "r"(v));
}
__device__ __forceinline__ float sigm(float x) { return 1.0f / (1.0f + expf(-x)); }

__device__ __forceinline__ void grid_bar() {
    __threadfence();
    __syncthreads();
    if (threadIdx.x == 0) {
        unsigned gen = *((volatile unsigned*)&g_gen);
        __threadfence();
        if (atomicAdd(&g_cnt, 1u) == (unsigned)(NB - 1)) {
            g_cnt = 0;
            __threadfence();
            atomicExch(&g_gen, gen + 1u);
        } else {
            int spins = 0;
            while (*((volatile unsigned*)&g_gen) == gen) {
                if (++spins > 8192) { __nanosleep(64); spins = 0; }
            }
        }
    }
    __syncthreads();
}

// ---------------- pack weights (transpose + gate-interleave) ----------------
// packed col p: q = p&3 (i,f,g,o), j = p>>2 ; orig gate row = q*H + j
__global__ void pack_kernel(const float* __restrict__ We,
                            const float* __restrict__ Wih_e, const float* __restrict__ Whh_e,
                            const float* __restrict__ bih_e, const float* __restrict__ bhh_e,
                            const float* __restrict__ Wd, const float* __restrict__ bd,
                            const float* __restrict__ Wih_d, const float* __restrict__ Whh_d,
                            const float* __restrict__ bih_d, const float* __restrict__ bhh_d,
                            const float* __restrict__ Wo) {
    const int R0 = Hh * G4;         // WhhTpE
    const int R1 = R0 + Ee * G4;    // WihTpE
    const int R2 = R1 + KD * G4;    // WsTpD
    const int R3 = R2 + Hh * Vv;    // WoT
    const int R4 = R3 + Vv * Ee;    // WdT
    const int R5 = R4 + Vv * Ee;    // WdTb
    const int R6 = R5 + Vv * Ee;    // WeT
    const int R7 = R6 + G4;         // biasE
    const int R8 = R7 + G4;         // biasD
    for (int id = blockIdx.x * blockDim.x + threadIdx.x; id < R8; id += gridDim.x * blockDim.x) {
        if (id < R0) {
            int k = id / G4, p = id % G4, q = p & 3, j = p >> 2;
            g_WhhTpE[id] = Whh_e[(q * Hh + j) * Hh + k];
        } else if (id < R1) {
            int t = id - R0; int e = t / G4, p = t % G4, q = p & 3, j = p >> 2;
            g_WihTpE[t] = Wih_e[(q * Hh + j) * Ee + e];
        } else if (id < R2) {
            int t = id - R1; int k = t / G4, p = t % G4, q = p & 3, j = p >> 2;
            g_WsTpD[t] = (k < Ee) ? Wih_d[(q * Hh + j) * Ee + k]
                                  : Whh_d[(q * Hh + j) * Hh + (k - Ee)];
        } else if (id < R3) {
            int t = id - R2; int k = t / Vv, v = t % Vv;
            g_WoT[t] = Wo[v * Hh + k];
        } else if (id < R4) {
            int t = id - R3; int v = t / Ee, e = t % Ee;
            g_WdT[t] = Wd[e * Vv + v];
        } else if (id < R5) {
            int t = id - R4; int v = t / Ee, e = t % Ee;
            g_WdTb[t] = Wd[e * Vv + v] + bd[e];
        } else if (id < R6) {
            int t = id - R5; int v = t / Ee, e = t % Ee;
            g_WeT[t] = We[e * Vv + v];
        } else if (id < R7) {
            int p = id - R6, q = p & 3, j = p >> 2;
            g_biasE[p] = bih_e[q * Hh + j] + bhh_e[q * Hh + j];
        } else {
            int p = id - R7, q = p & 3, j = p >> 2;
            g_biasD[p] = bih_d[q * Hh + j] + bhh_d[q * Hh + j];
        }
    }
}

// ---------------- Xe = x @ We^T + be ----------------
__global__ void __launch_bounds__(256) xe_kernel(const float* __restrict__ x,
                                                 const float* __restrict__ be) {
    __shared__ float As[32][65];
    __shared__ float Bs[32][64];
    int tid = threadIdx.x;
    int tx = tid & 15, ty = tid >> 4;
    int m0 = blockIdx.x * 64;
    float acc[4][4];
#pragma unroll
    for (int c = 0; c < 4; c++) {
        float b = be[tx * 4 + c];
#pragma unroll
        for (int r = 0; r < 4; r++) acc[r][c] = b;
    }
    for (int kt = 0; kt < 16; ++kt) {
        int k0 = kt * 32;
        {
            int kk = tid & 31, mm = tid >> 5;
#pragma unroll
            for (int p = 0; p < 8; p++) {
                int m = mm + p * 8;
                As[kk][m] = x[(size_t)(m0 + m) * Vv + k0 + kk];
            }
        }
        {
            int ee = tid & 63, kk = tid >> 6;
#pragma unroll
            for (int p = 0; p < 8; p++) {
                int k = kk + p * 4;
                Bs[k][ee] = g_WeT[(size_t)(k0 + k) * Ee + ee];
            }
        }
        __syncthreads();
#pragma unroll
        for (int kk = 0; kk < 32; kk++) {
            float a[4], b[4];
#pragma unroll
            for (int r = 0; r < 4; r++) a[r] = As[kk][ty * 4 + r];
#pragma unroll
            for (int c = 0; c < 4; c++) b[c] = Bs[kk][tx * 4 + c];
#pragma unroll
            for (int r = 0; r < 4; r++)
#pragma unroll
                for (int c = 0; c < 4; c++) acc[r][c] += a[r] * b[c];
        }
        __syncthreads();
    }
#pragma unroll
    for (int r = 0; r < 4; r++) {
        int m = m0 + ty * 4 + r;
#pragma unroll
        for (int c = 0; c < 4; c++) g_Xe[(size_t)m * Ee + tx * 4 + c] = acc[r][c];
    }
}

// ---------------- Gx = Xe @ WihTpE + biasE  (output permuted [t][b][p]) ----------------
__global__ void __launch_bounds__(256) gx_kernel() {
    __shared__ float As[64][65];
    __shared__ float Bs[64][64];
    int tid = threadIdx.x;
    int tx = tid & 15, ty = tid >> 4;
    int m0 = blockIdx.x * 64;
    int n0 = blockIdx.y * 64;
    {
        int kk = tid & 63, mm = tid >> 6;
#pragma unroll
        for (int p = 0; p < 16; p++) {
            int m = mm + p * 4;
            As[kk][m] = g_Xe[(size_t)(m0 + m) * Ee + kk];
        }
    }
    {
        int nn = tid & 63, kk = tid >> 6;
#pragma unroll
        for (int p = 0; p < 16; p++) {
            int k = kk + p * 4;
            Bs[k][nn] = g_WihTpE[(size_t)k * G4 + n0 + nn];
        }
    }
    __syncthreads();
    float acc[4][4];
#pragma unroll
    for (int c = 0; c < 4; c++) {
        float b = g_biasE[n0 + tx * 4 + c];
#pragma unroll
        for (int r = 0; r < 4; r++) acc[r][c] = b;
    }
#pragma unroll
    for (int kk = 0; kk < 64; kk++) {
        float a[4], b[4];
#pragma unroll
        for (int r = 0; r < 4; r++) a[r] = As[kk][ty * 4 + r];
#pragma unroll
        for (int c = 0; c < 4; c++) b[c] = Bs[kk][tx * 4 + c];
#pragma unroll
        for (int r = 0; r < 4; r++)
#pragma unroll
            for (int c = 0; c < 4; c++) acc[r][c] += a[r] * b[c];
    }
#pragma unroll
    for (int r = 0; r < 4; r++) {
        int bt = m0 + ty * 4 + r;
        int b = bt >> 7, t = bt & 127;
        size_t base = ((size_t)t * Bb + b) * G4 + n0 + tx * 4;
#pragma unroll
        for (int c = 0; c < 4; c++) g_Gx[base + c] = acc[r][c];
    }
}

// ---------------- emb0 ----------------
__global__ void emb0_kernel(const float* __restrict__ x, const float* __restrict__ bd) {
    __shared__ float x0[Vv];
    int b = blockIdx.x, tid = threadIdx.x; // 64 threads
    for (int i = tid; i < Vv; i += 64) x0[i] = x[(size_t)b * Tt * Vv + i];
    __syncthreads();
    float acc = bd[tid];
    for (int v = 0; v < Vv; v++) acc += x0[v] * g_WdT[(size_t)v * Ee + tid];
    g_emb[b * Ee + tid] = acc;
}

// ---------------- init ----------------
__global__ void init_kernel(const int* __restrict__ xlens, float* __restrict__ out,
                            int write_extra) {
    int id = blockIdx.x * blockDim.x + threadIdx.x;
    if (id < Bb * Vv) {
        int b = id / Vv, v = id % Vv;
        out[(size_t)b * Tt * Vv + v] = 0.f;
    }
    if (write_extra && id < Bb) out[(size_t)Bb * Tt * Vv + id] = (float)xlens[id];
    if (id < Bb * Hh) { g_h[0][id] = 0.f; g_h[1][id] = 0.f; }
}

// ---------------- persistent recurrent kernel ----------------
__global__ void __launch_bounds__(NT, 1) rec_kernel(const int* __restrict__ xlens,
                                                    const float* __restrict__ bo,
                                                    float* __restrict__ out,
                                                    int write_extra) {
    extern __shared__ float dsm[];
    float* Ws = dsm;                       // [320][34] weights (enc uses 256 rows)
    float* As = dsm + AS_OFF;              // 2 x [32][66] double buffer
    float* WoS = dsm + WOS_OFF;            // [256][34] Wo slice (staged once)
    float* hs = dsm + HS_OFF;              // [32][264] phase2 h tile
    int* sIdx = (int*)(dsm + SIDX_OFF);    // [64]

    const int tid = threadIdx.x, bx = blockIdx.x;
    const int tx = tid & 15, ty = tid >> 4;
    const int m0 = (bx >> 5) * 64;
    const int n0 = (bx & 31) * 32;
    const int row0 = m0 + ty * 4;
    const int col0 = n0 + tx * 2;
    const bool evenT = ((tx & 1) == 0);
    const int junit = col0 >> 2;
    const int skk = tid & 31, smm = tid >> 5;

    float c_reg[4] = {0.f, 0.f, 0.f, 0.f};
    float h_reg[4] = {0.f, 0.f, 0.f, 0.f};
    int lens[4];
#pragma unroll
    for (int r = 0; r < 4; r++) lens[r] = xlens[row0 + r];

    const unsigned FULL = 0xffffffffu;
    int par = 0;

    // ---- stage encoder Whh tile [256][32] ----
    for (int i = tid; i < Hh * 32; i += NT) {
        int k = i >> 5, n = i & 31;
        Ws[k * WS_STRIDE + n] = g_WhhTpE[(size_t)k * G4 + n0 + n];
    }
    __syncthreads();

    // ======================= encoder =======================
    for (int t = 0; t < Tt; ++t) {
        float acc[4][2];
        const float* gx = g_Gx + ((size_t)t * Bb) * G4;
#pragma unroll
        for (int r = 0; r < 4; r++) {
            acc[r][0] = __ldg(&gx[(size_t)(row0 + r) * G4 + col0]);
            acc[r][1] = __ldg(&gx[(size_t)(row0 + r) * G4 + col0 + 1]);
        }
        const float* hbuf = g_h[par];
        // stage ktile 0
        {
            const float* src = hbuf + (size_t)(m0 + smm) * Hh + skk;
            float* dst = As + skk * AST + smm;
#pragma unroll
            for (int p = 0; p < 8; p++) dst[p * 8] = ldcg(src + (size_t)(p * 8) * Hh);
        }
        __syncthreads();
        int buf = 0;
        for (int kt = 0; kt < NKT_E; ++kt) {
            if (kt + 1 < NKT_E) {
                int k0n = (kt + 1) * KT;
                const float* src = hbuf + (size_t)(m0 + smm) * Hh + k0n + skk;
                float* dst = As + (buf ^ 1) * AS_BUF + skk * AST + smm;
#pragma unroll
                for (int p = 0; p < 8; p++) dst[p * 8] = ldcg(src + (size_t)(p * 8) * Hh);
            }
            const float* Ab = As + buf * AS_BUF;
            const float* Wk = Ws + (kt * KT) * WS_STRIDE;
#pragma unroll
            for (int kk = 0; kk < KT; kk++) {
                float2 b2 = *(const float2*)&Wk[kk * WS_STRIDE + tx * 2];
                float2 alo = *(const float2*)&Ab[kk * AST + ty * 4];
                float2 ahi = *(const float2*)&Ab[kk * AST + ty * 4 + 2];
                acc[0][0] += alo.x * b2.x; acc[0][1] += alo.x * b2.y;
                acc[1][0] += alo.y * b2.x; acc[1][1] += alo.y * b2.y;
                acc[2][0] += ahi.x * b2.x; acc[2][1] += ahi.x * b2.y;
                acc[3][0] += ahi.y * b2.x; acc[3][1] += ahi.y * b2.y;
            }
            __syncthreads();
            buf ^= 1;
        }
#pragma unroll
        for (int r = 0; r < 4; r++) {
            float gg = __shfl_down_sync(FULL, acc[r][0], 1);
            float go = __shfl_down_sync(FULL, acc[r][1], 1);
            if (evenT) {
                float i_ = sigm(acc[r][0]), f_ = sigm(acc[r][1]);
                float gv = tanhf(gg), o_ = sigm(go);
                float cn = f_ * c_reg[r] + i_ * gv;
                float hn = o_ * tanhf(cn);
                bool msk = (t < lens[r]);
                c_reg[r] = msk ? cn : c_reg[r];
                float hv = msk ? hn : h_reg[r];
                h_reg[r] = hv;
                stcg(&g_h[par ^ 1][(size_t)(row0 + r) * Hh + junit], hv);
            }
        }
        grid_bar();
        par ^= 1;
    }

    if (write_extra && evenT) {
#pragma unroll
        for (int r = 0; r < 4; r++)
            out[(size_t)Bb * Tt * Vv + Bb + (size_t)(row0 + r) * Hh + junit] = h_reg[r];
    }

    // ---- stage decoder stacked weight tile [320][32] + Wo slice (once) ----
    __syncthreads();
    for (int i = tid; i < KD * 32; i += NT) {
        int k = i >> 5, n = i & 31;
        Ws[k * WS_STRIDE + n] = g_WsTpD[(size_t)k * G4 + n0 + n];
    }
    const float biasD0 = g_biasD[col0], biasD1 = g_biasD[col0 + 1];
    // phase2 constants: 16 col groups x 8 row groups
    const int colg = bx & 15, rowg = bx >> 4;
    const int r0p2 = rowg * 32;
    const int t16 = tid & 15, rq = tid >> 4;
    const int cloc = t16 * 2;
    const int cglob = colg * 32 + cloc;
    for (int i = tid; i < Hh * 32; i += NT) {
        int k = i >> 5, c = i & 31;
        WoS[k * WOS_STRIDE + c] = g_WoT[(size_t)k * Vv + colg * 32 + c];
    }
    const float bo0 = __ldg(&bo[cglob]);
    const float bo1 = __ldg(&bo[cglob + 1]);
    __syncthreads();

    // ======================= decoder =======================
    for (int s = 0; s < Tt - 1; ++s) {
        // combine group argmaxes from previous step
        if (s > 0) {
            if (tid < 64) {
                int row = m0 + tid;
                float best = ldcg(&g_av16[row]); int bi = ldcg_i(&g_ai16[row]);
#pragma unroll
                for (int g = 1; g < 16; g++) {
                    float v = ldcg(&g_av16[g * Bb + row]);
                    int ix = ldcg_i(&g_ai16[g * Bb + row]);
                    if (v > best) { best = v; bi = ix; }
                }
                sIdx[tid] = bi;
            }
            __syncthreads();
        }

        float acc[4][2];
#pragma unroll
        for (int r = 0; r < 4; r++) { acc[r][0] = biasD0; acc[r][1] = biasD1; }
        const float* hbuf = g_h[par];

        // stage ktile 0 (emb region)
        {
            float* dst = As + skk * AST + smm;
            if (s == 0) {
                const float* src = g_emb + (size_t)(m0 + smm) * Ee + skk;
#pragma unroll
                for (int p = 0; p < 8; p++) dst[p * 8] = ldcg(src + (size_t)(p * 8) * Ee);
            } else {
#pragma unroll
                for (int p = 0; p < 8; p++) {
                    int idx = sIdx[smm + p * 8];
                    dst[p * 8] = __ldg(&g_WdTb[(size_t)idx * Ee + skk]);
                }
            }
        }
        __syncthreads();
        int buf = 0;
        for (int kt = 0; kt < NKT_D; ++kt) {
            if (kt + 1 < NKT_D) {
                int k0n = (kt + 1) * KT;
                float* dst = As + (buf ^ 1) * AS_BUF + skk * AST + smm;
                if (k0n < Ee) {
                    if (s == 0) {
                        const float* src = g_emb + (size_t)(m0 + smm) * Ee + k0n + skk;
#pragma unroll
                        for (int p = 0; p < 8; p++) dst[p * 8] = ldcg(src + (size_t)(p * 8) * Ee);
                    } else {
#pragma unroll
                        for (int p = 0; p < 8; p++) {
                            int idx = sIdx[smm + p * 8];
                            dst[p * 8] = __ldg(&g_WdTb[(size_t)idx * Ee + k0n + skk]);
                        }
                    }
                } else {
                    const float* src = hbuf + (size_t)(m0 + smm) * Hh + (k0n - Ee) + skk;
#pragma unroll
                    for (int p = 0; p < 8; p++) dst[p * 8] = ldcg(src + (size_t)(p * 8) * Hh);
                }
            }
            const float* Ab = As + buf * AS_BUF;
            const float* Wk = Ws + (kt * KT) * WS_STRIDE;
#pragma unroll
            for (int kk = 0; kk < KT; kk++) {
                float2 b2 = *(const float2*)&Wk[kk * WS_STRIDE + tx * 2];
                float2 alo = *(const float2*)&Ab[kk * AST + ty * 4];
                float2 ahi = *(const float2*)&Ab[kk * AST + ty * 4 + 2];
                acc[0][0] += alo.x * b2.x; acc[0][1] += alo.x * b2.y;
                acc[1][0] += alo.y * b2.x; acc[1][1] += alo.y * b2.y;
                acc[2][0] += ahi.x * b2.x; acc[2][1] += ahi.x * b2.y;
                acc[3][0] += ahi.y * b2.x; acc[3][1] += ahi.y * b2.y;
            }
            __syncthreads();
            buf ^= 1;
        }
#pragma unroll
        for (int r = 0; r < 4; r++) {
            float gg = __shfl_down_sync(FULL, acc[r][0], 1);
            float go = __shfl_down_sync(FULL, acc[r][1], 1);
            if (evenT) {
                float i_ = sigm(acc[r][0]), f_ = sigm(acc[r][1]);
                float gv = tanhf(gg), o_ = sigm(go);
                float cn = f_ * c_reg[r] + i_ * gv;
                float hn = o_ * tanhf(cn);
                c_reg[r] = cn;
                h_reg[r] = hn;
                stcg(&g_h[par ^ 1][(size_t)(row0 + r) * Hh + junit], hn);
            }
        }
        grid_bar();
        par ^= 1;

        // ---- phase2: logits 32 rows x 32 cols per block (Wo resident in smem) ----
        {
            const float* hb = g_h[par];
            {
                int row = tid >> 3, kb = tid & 7;
                const float* src = hb + (size_t)(r0p2 + row) * Hh + kb;
                float* dst = hs + row * HS_STRIDE + kb;
#pragma unroll
                for (int q = 0; q < 32; q++) dst[q * 8] = ldcg(src + q * 8);
            }
            __syncthreads();
            const float* hA = hs + (rq * 2) * HS_STRIDE;
            const float* hB = hA + HS_STRIDE;
            float a0 = bo0, a1 = bo1, b0 = bo0, b1 = bo1;
#pragma unroll 8
            for (int k = 0; k < Hh; k++) {
                float w0 = WoS[k * WOS_STRIDE + cloc];
                float w1 = WoS[k * WOS_STRIDE + cloc + 1];
                float ha = hA[k], hbv = hB[k];
                a0 += ha * w0; a1 += ha * w1;
                b0 += hbv * w0; b1 += hbv * w1;
            }
            int rA = r0p2 + rq * 2, rB = rA + 1;
            size_t ybA = (size_t)rA * Tt * Vv + (size_t)(s + 1) * Vv + cglob;
            size_t ybB = (size_t)rB * Tt * Vv + (size_t)(s + 1) * Vv + cglob;
            out[ybA] = a0; out[ybA + 1] = a1;
            out[ybB] = b0; out[ybB + 1] = b1;
            // local argmax over 2 cols, reduce over 16 lanes
            float vA = a0; int iA = cglob; if (a1 > vA) { vA = a1; iA = cglob + 1; }
            float vB = b0; int iB = cglob; if (b1 > vB) { vB = b1; iB = cglob + 1; }
#pragma unroll
            for (int off = 8; off > 0; off >>= 1) {
                float ov = __shfl_down_sync(FULL, vA, off, 16);
                int oi = __shfl_down_sync(FULL, iA, off, 16);
                if (ov > vA || (ov == vA && oi < iA)) { vA = ov; iA = oi; }
                ov = __shfl_down_sync(FULL, vB, off, 16);
                oi = __shfl_down_sync(FULL, iB, off, 16);
                if (ov > vB || (ov == vB && oi < iB)) { vB = ov; iB = oi; }
            }
            if (t16 == 0) {
                stcg(&g_av16[colg * Bb + rA], vA);
                stcg_i(&g_ai16[colg * Bb + rA], iA);
                stcg(&g_av16[colg * Bb + rB], vB);
                stcg_i(&g_ai16[colg * Bb + rB], iB);
            }
        }
        grid_bar();
    }
}

// ---------------- launch ----------------
extern "C" void kernel_launch(void* const* d_in, const int* in_sizes, int n_in,
                              void* d_out, int out_size) {
    (void)in_sizes; (void)n_in;
    const float* x     = (const float*)d_in[0];
    const int*   xlens = (const int*)  d_in[1];
    const float* We    = (const float*)d_in[2];
    const float* be    = (const float*)d_in[3];
    const float* Wih_e = (const float*)d_in[4];
    const float* Whh_e = (const float*)d_in[5];
    const float* bih_e = (const float*)d_in[6];
    const float* bhh_e = (const float*)d_in[7];
    const float* Wd    = (const float*)d_in[8];
    const float* bd    = (const float*)d_in[9];
    const float* Wih_d = (const float*)d_in[10];
    const float* Whh_d = (const float*)d_in[11];
    const float* bih_d = (const float*)d_in[12];
    const float* bhh_d = (const float*)d_in[13];
    const float* Wo    = (const float*)d_in[14];
    const float* bo    = (const float*)d_in[15];
    float* out = (float*)d_out;

    int write_extra = (out_size >= Bb * Tt * Vv + Bb + Bb * Hh) ? 1 : 0;

    cudaFuncSetAttribute(rec_kernel, cudaFuncAttributeMaxDynamicSharedMemorySize, DSM_BYTES);

    pack_kernel<<<1024, 256>>>(We, Wih_e, Whh_e, bih_e, bhh_e,
                               Wd, bd, Wih_d, Whh_d, bih_d, bhh_d, Wo);
    xe_kernel<<<512, 256>>>(x, be);
    gx_kernel<<<dim3(512, 16), 256>>>();
    emb0_kernel<<<Bb, 64>>>(x, bd);
    init_kernel<<<512, 256>>>(xlens, out, write_extra);
    rec_kernel<<<NB, NT, DSM_BYTES>>>(xlens, bo, out, write_extra);
}